// round 6
// baseline (speedup 1.0000x reference)
#include <cuda_runtime.h>
#include <cuda_fp16.h>
#include <math.h>

// Fixed shapes: features [16,512,768] f32, labels [16,512] i32. N = 8192.
#define H      768
#define NCLS   10
#define TPB    256
#define NBLK   512            // all co-resident: smem 30.7KB -> 7 blocks/SM, 512 < 148*7
#define RPB    16             // rows per block (N = NBLK*RPB = 8192)
#define RPI    8
#define ITERS  (RPB / RPI)    // 2
#define CH     (NCLS * H)     // 7680
#define CH2    (CH / 2)       // 3840 half2 per partial
#define NSLICE (CH2 / TPB)    // 15
#define RGRP   32             // partials per reduce group
#define NGRP   (NBLK / RGRP)  // 16
#define NRED   (NGRP * NSLICE)// 240 reduce blocks
#define TEMPERATURE 0.07f
#define EPS    1e-12f

// Device scratch. Counter/accumulator state is zero at load and restored to
// zero by the last block each run (self-cleaning for graph replay).
__device__ __half2  g_part[NBLK * CH2];  // fp16 per-block class sums (7.9 MB)
__device__ float    g_cs  [CH];
__device__ int      g_cnt_tot[NCLS];
__device__ unsigned g_arrived = 0;
__device__ unsigned g_done    = 0;

__global__ __launch_bounds__(TPB) void supcon_one(
    const float* __restrict__ feat,
    const int*   __restrict__ labels,
    float*       __restrict__ out,
    int out_size, int N)
{
    __shared__ float acc[CH];        // 30720 B
    __shared__ float redf[RPI * 8];
    __shared__ float inv[RPI];
    __shared__ int   labs[RPI];
    __shared__ int   cnts[NCLS];
    __shared__ unsigned ticket_sh;
    __shared__ float sredA[8];
    __shared__ float sredP[8];
    __shared__ float loss_sh;

    const int tid  = threadIdx.x;
    const int lane = tid & 31;
    const int warp = tid >> 5;
    const int bid  = blockIdx.x;

    // ================= Phase 1: per-block class accumulation ===============
    for (int i = tid; i < CH; i += TPB) acc[i] = 0.0f;
    if (tid < NCLS) cnts[tid] = 0;
    __syncthreads();

    const int row0 = bid * RPB;
    for (int it = 0; it < ITERS; ++it) {
        const int base = row0 + it * RPI;

        float v[RPI][3];
        float ss[RPI];
        #pragma unroll
        for (int j = 0; j < RPI; ++j) {
            const float* x = feat + (size_t)(base + j) * H;
            v[j][0] = x[tid];
            v[j][1] = x[tid + 256];
            v[j][2] = x[tid + 512];
        }
        if (tid < RPI) {
            int l = labels[base + tid];
            labs[tid] = min(max(l, 0), NCLS - 1);
        }
        #pragma unroll
        for (int j = 0; j < RPI; ++j)
            ss[j] = v[j][0]*v[j][0] + v[j][1]*v[j][1] + v[j][2]*v[j][2];
        #pragma unroll
        for (int o = 16; o > 0; o >>= 1) {
            #pragma unroll
            for (int j = 0; j < RPI; ++j)
                ss[j] += __shfl_xor_sync(0xffffffffu, ss[j], o);
        }
        if (lane == 0) {
            #pragma unroll
            for (int j = 0; j < RPI; ++j) redf[j * 8 + warp] = ss[j];
        }
        __syncthreads();
        if (tid < RPI * 8) {
            float s = redf[tid];
            s += __shfl_xor_sync(0xffffffffu, s, 4);
            s += __shfl_xor_sync(0xffffffffu, s, 2);
            s += __shfl_xor_sync(0xffffffffu, s, 1);
            if ((tid & 7) == 0)
                inv[tid >> 3] = 1.0f / fmaxf(sqrtf(s), EPS);
        }
        __syncthreads();
        #pragma unroll
        for (int j = 0; j < RPI; ++j) {
            const float iv = inv[j];
            float* a = acc + labs[j] * H;
            a[tid]       += v[j][0] * iv;
            a[tid + 256] += v[j][1] * iv;
            a[tid + 512] += v[j][2] * iv;
        }
        if (tid < RPI) atomicAdd(&cnts[labs[tid]], 1);
        __syncthreads();
    }

    // Flush partials as fp16 (half traffic; stays L2-resident).
    {
        __half2* dst = g_part + (size_t)bid * CH2;
        #pragma unroll
        for (int k = 0; k < NSLICE; ++k) {
            const int i = k * TPB + tid;
            dst[i] = __floats2half2_rn(acc[2 * i], acc[2 * i + 1]);
        }
        if (tid < NCLS && cnts[tid] > 0) atomicAdd(&g_cnt_tot[tid], cnts[tid]);
    }

    // Arrive (release).
    __threadfence();
    __syncthreads();
    if (tid == 0) atomicAdd(&g_arrived, 1u);

    if (bid >= NRED) return;   // non-reduce blocks exit, freeing SMs

    // ================= Phase 2: wait + parallel reduce ======================
    if (tid == 0) {
        volatile unsigned* p = &g_arrived;
        while (*p < NBLK) __nanosleep(64);
    }
    __syncthreads();
    __threadfence();   // acquire

    {
        const int s   = bid % NSLICE;
        const int grp = bid / NSLICE;
        const int i   = s * TPB + tid;                 // half2 index in [0,CH2)
        const __half2* base = g_part + (size_t)grp * RGRP * CH2 + i;
        float sx = 0.0f, sy = 0.0f;
        #pragma unroll
        for (int b = 0; b < RGRP; ++b) {
            float2 f = __half22float2(base[(size_t)b * CH2]);
            sx += f.x;
            sy += f.y;
        }
        atomicAdd(&g_cs[2 * i],     sx);
        atomicAdd(&g_cs[2 * i + 1], sy);
    }

    // Last-block-done ticket.
    __threadfence();
    __syncthreads();
    if (tid == 0) ticket_sh = atomicAdd(&g_done, 1u);
    __syncthreads();
    if (ticket_sh != NRED - 1) return;
    __threadfence();   // acquire all g_cs adds

    // ================= Phase 3: epilogue (f32) ==============================
    float p_all = 0.0f, p_pos = 0.0f;
    #pragma unroll
    for (int k = 0; k < H / TPB; ++k) {          // 3 iterations
        const int h = k * TPB + tid;
        float sh = 0.0f;
        #pragma unroll
        for (int c = 0; c < NCLS; ++c) {
            float vv = g_cs[c * H + h];
            sh    += vv;
            p_pos += vv * vv;
        }
        p_all += sh * sh;
    }
    #pragma unroll
    for (int o = 16; o > 0; o >>= 1) {
        p_all += __shfl_xor_sync(0xffffffffu, p_all, o);
        p_pos += __shfl_xor_sync(0xffffffffu, p_pos, o);
    }
    if (lane == 0) { sredA[warp] = p_all; sredP[warp] = p_pos; }
    __syncthreads();

    if (tid == 0) {
        float A = 0.0f, P = 0.0f;
        #pragma unroll
        for (int w = 0; w < 8; ++w) { A += sredA[w]; P += sredP[w]; }
        float n_pos = 0.0f;
        #pragma unroll
        for (int c = 0; c < NCLS; ++c) {
            float nc = (float)g_cnt_tot[c];
            n_pos += nc * nc;
        }
        float Nf    = (float)N;
        float n_neg = Nf * Nf - n_pos;

        float pos_mean = (P / TEMPERATURE) / n_pos;
        float neg_mean = ((A - P) / TEMPERATURE) / n_neg;
        float d = neg_mean - pos_mean;
        loss_sh = (d > 0.0f) ? d + log1pf(expf(-d)) : log1pf(expf(d));
    }
    __syncthreads();
    for (int i = tid; i < out_size; i += TPB) out[i] = loss_sh;

    // Self-clean scratch for the next graph replay.
    for (int i = tid; i < CH; i += TPB) g_cs[i] = 0.0f;
    if (tid < NCLS) g_cnt_tot[tid] = 0;
    if (tid == 0) { g_arrived = 0u; g_done = 0u; }
}

// ---------------------------------------------------------------------------
extern "C" void kernel_launch(void* const* d_in, const int* in_sizes, int n_in,
                              void* d_out, int out_size)
{
    const float* feat   = (const float*)d_in[0];
    const int*   labels = (const int*)d_in[1];
    float*       out    = (float*)d_out;
    const int N = in_sizes[1];   // 8192

    supcon_one<<<NBLK, TPB>>>(feat, labels, out, out_size, N);
}

// round 7
// speedup vs baseline: 1.0381x; 1.0381x over previous
#include <cuda_runtime.h>
#include <cuda_fp16.h>
#include <math.h>

// Fixed shapes: features [16,512,768] f32, labels [16,512] i32. N = 8192.
#define H      768
#define H4     (H / 4)         // 192 float4 per row
#define NCLS   10
#define TPB    256
#define NBLK   512             // accumulation blocks
#define RPB    16              // rows per block (N = NBLK*RPB = 8192)
#define RPW    2               // rows per warp (8 warps * 2 = 16)
#define CH     (NCLS * H)      // 7680
#define CH2    (CH / 2)        // 3840 half2 per partial
#define NSLICE (CH2 / TPB)     // 15
#define RGRP   32              // partials per reduce group
#define NGRP   (NBLK / RGRP)   // 16
#define NRED   (NGRP * NSLICE) // 240 reduce blocks
#define TEMPERATURE 0.07f
#define EPS    1e-12f

// Device scratch. g_cs/g_done/g_cnt_tot zero at load, restored by last block.
__device__ __half2  g_part[NBLK * CH2];   // fp16 per-block class sums (7.9 MB)
__device__ float    g_cs  [CH];
__device__ int      g_cnt_tot[NCLS];
__device__ unsigned g_done = 0;

// ---------------------------------------------------------------------------
// Kernel 1: Phase A = warp-local row norms (float4, no block syncs).
//           Phase B = owner-h accumulation from hot L2 (one sync total).
// ---------------------------------------------------------------------------
__global__ __launch_bounds__(TPB, 4) void supcon_accum(
    const float* __restrict__ feat,
    const int*   __restrict__ labels)
{
    __shared__ float acc[CH];       // 30720 B
    __shared__ float inv[RPB];
    __shared__ int   labs[RPB];

    const int tid  = threadIdx.x;
    const int lane = tid & 31;
    const int warp = tid >> 5;
    const int bid  = blockIdx.x;
    const int row0 = bid * RPB;

    // Zero class accumulators.
    for (int i = tid; i < CH; i += TPB) acc[i] = 0.0f;

    // Labels for the block's 16 rows (clamped; consumed after the sync).
    if (tid < RPB) {
        int l = labels[row0 + tid];
        labs[tid] = min(max(l, 0), NCLS - 1);
    }

    // ---- Phase A: each warp computes norms of its 2 rows (warp-only) ----
    #pragma unroll
    for (int rr = 0; rr < RPW; ++rr) {
        const int r = warp * RPW + rr;
        const float4* x4 = reinterpret_cast<const float4*>(
                               feat + (size_t)(row0 + r) * H);
        float4 v[6];
        #pragma unroll
        for (int j = 0; j < 6; ++j)          // 6 independent LDG.128
            v[j] = x4[j * 32 + lane];
        float ss = 0.0f;
        #pragma unroll
        for (int j = 0; j < 6; ++j)
            ss += v[j].x*v[j].x + v[j].y*v[j].y + v[j].z*v[j].z + v[j].w*v[j].w;
        #pragma unroll
        for (int o = 16; o > 0; o >>= 1)
            ss += __shfl_xor_sync(0xffffffffu, ss, o);
        if (lane == 0)
            inv[r] = 1.0f / fmaxf(sqrtf(ss), EPS);
    }
    __syncthreads();   // the only barrier before the flush

    // ---- Phase B: accumulate normalized rows (reads hit L2) ----
    // Thread owns h = {tid, tid+256, tid+512}: no smem races, no barriers.
    #pragma unroll
    for (int r0 = 0; r0 < RPB; r0 += 4) {
        float v[4][3];
        #pragma unroll
        for (int j = 0; j < 4; ++j) {        // 12 loads in flight
            const float* x = feat + (size_t)(row0 + r0 + j) * H;
            v[j][0] = x[tid];
            v[j][1] = x[tid + 256];
            v[j][2] = x[tid + 512];
        }
        #pragma unroll
        for (int j = 0; j < 4; ++j) {
            const float iv = inv[r0 + j];
            float* a = acc + labs[r0 + j] * H;
            a[tid]       += v[j][0] * iv;
            a[tid + 256] += v[j][1] * iv;
            a[tid + 512] += v[j][2] * iv;
        }
    }
    __syncthreads();

    // ---- Flush fp16 partials + class counts ----
    __half2* dst = g_part + (size_t)bid * CH2;
    #pragma unroll
    for (int k = 0; k < NSLICE; ++k) {
        const int i = k * TPB + tid;
        dst[i] = __floats2half2_rn(acc[2 * i], acc[2 * i + 1]);
    }
    if (tid < NCLS) {
        int c = 0;
        #pragma unroll
        for (int r = 0; r < RPB; ++r) c += (labs[r] == tid);
        if (c > 0) atomicAdd(&g_cnt_tot[tid], c);
    }
}

// ---------------------------------------------------------------------------
// Kernel 2: reduce fp16 partials -> g_cs, last block computes loss (f32).
// ---------------------------------------------------------------------------
__global__ __launch_bounds__(TPB) void supcon_reduce_final(
    float* __restrict__ out, int out_size, int N)
{
    __shared__ unsigned ticket_sh;
    __shared__ float sredA[8];
    __shared__ float sredP[8];
    __shared__ float loss_sh;

    const int tid  = threadIdx.x;
    const int lane = tid & 31;
    const int warp = tid >> 5;
    const int bid  = blockIdx.x;

    // Reduce this block's slice of 32 partials (L2-resident).
    {
        const int s   = bid % NSLICE;
        const int grp = bid / NSLICE;
        const int i   = s * TPB + tid;                  // half2 index
        const __half2* base = g_part + (size_t)grp * RGRP * CH2 + i;
        float sx = 0.0f, sy = 0.0f;
        #pragma unroll
        for (int b = 0; b < RGRP; ++b) {
            float2 f = __half22float2(base[(size_t)b * CH2]);
            sx += f.x;
            sy += f.y;
        }
        atomicAdd(&g_cs[2 * i],     sx);
        atomicAdd(&g_cs[2 * i + 1], sy);
    }

    // Last-block-done ticket.
    __threadfence();
    __syncthreads();
    if (tid == 0) ticket_sh = atomicAdd(&g_done, 1u);
    __syncthreads();
    if (ticket_sh != NRED - 1) return;
    __threadfence();   // acquire all g_cs adds

    // ---- Epilogue (f32) ----
    float p_all = 0.0f, p_pos = 0.0f;
    #pragma unroll
    for (int k = 0; k < H / TPB; ++k) {
        const int h = k * TPB + tid;
        float sh = 0.0f;
        #pragma unroll
        for (int c = 0; c < NCLS; ++c) {
            float vv = g_cs[c * H + h];
            sh    += vv;
            p_pos += vv * vv;
        }
        p_all += sh * sh;
    }
    #pragma unroll
    for (int o = 16; o > 0; o >>= 1) {
        p_all += __shfl_xor_sync(0xffffffffu, p_all, o);
        p_pos += __shfl_xor_sync(0xffffffffu, p_pos, o);
    }
    if (lane == 0) { sredA[warp] = p_all; sredP[warp] = p_pos; }
    __syncthreads();

    if (tid == 0) {
        float A = 0.0f, P = 0.0f;
        #pragma unroll
        for (int w = 0; w < 8; ++w) { A += sredA[w]; P += sredP[w]; }
        float n_pos = 0.0f;
        #pragma unroll
        for (int c = 0; c < NCLS; ++c) {
            float nc = (float)g_cnt_tot[c];
            n_pos += nc * nc;
        }
        float Nf    = (float)N;
        float n_neg = Nf * Nf - n_pos;

        float pos_mean = (P / TEMPERATURE) / n_pos;
        float neg_mean = ((A - P) / TEMPERATURE) / n_neg;
        float d = neg_mean - pos_mean;
        loss_sh = (d > 0.0f) ? d + log1pf(expf(-d)) : log1pf(expf(d));
    }
    __syncthreads();
    for (int i = tid; i < out_size; i += TPB) out[i] = loss_sh;

    // Self-clean scratch for the next graph replay.
    for (int i = tid; i < CH; i += TPB) g_cs[i] = 0.0f;
    if (tid < NCLS) g_cnt_tot[tid] = 0;
    if (tid == 0)   g_done = 0u;
}

// ---------------------------------------------------------------------------
extern "C" void kernel_launch(void* const* d_in, const int* in_sizes, int n_in,
                              void* d_out, int out_size)
{
    const float* feat   = (const float*)d_in[0];
    const int*   labels = (const int*)d_in[1];
    float*       out    = (float*)d_out;
    const int N = in_sizes[1];   // 8192

    supcon_accum       <<<NBLK, TPB>>>(feat, labels);
    supcon_reduce_final<<<NRED, TPB>>>(out, out_size, N);
}